// round 16
// baseline (speedup 1.0000x reference)
#include <cuda_runtime.h>
#include <cuda_bf16.h>
#include <cstdint>

#define B     8192
#define DDIM  256
#define BM    64
#define BN    64
#define COLSPLIT 2
#define COLS_PER_CTA (B / COLSPLIT)   // 4096
#define NT    (COLS_PER_CTA / BN)     // 64 col tiles
#define KSTEPS 8                      // K = 256 int8, k32 per mma
#define THREADS 128
#define K2E   28.853900817779268f     // 20 * log2(e)
#define LN2   0.6931471805599453f
#define MASKV (-1e38f)
// SMEM layout (bytes)
#define SM_A    0                     // 64 rows * 256 B = 16384
#define SM_B0   16384                 // 64 * 256 B = 16384
#define SM_B1   32768
#define SM_META 49152                 // 2 * (64 f32 base2 + 64 i32 lab + 64 f32 scale) = 1536
#define SM_RED  50688                 // 2 * 64 * float2 = 1024
#define SM_TOTAL 51712

// ---------------- scratch ----------------
__device__ uint2 g_q[B * 32];     // int8 rows, 256 B each
__device__ float g_basec[B];      // -10*||x||^2           (ln domain, numerator)
__device__ float g_basel2[B];     // -10*log2(e)*||x||^2   (log2 domain, lse)
__device__ float g_scale[B];      // per-row int8 scale
__device__ int   g_lab[B];
__device__ int   g_jsel[B];
__device__ int   g_valid[B];
__device__ float g_num[B];
__device__ float g_pm[COLSPLIT][B];
__device__ float g_ps[COLSPLIT][B];
__device__ int   g_lab64;
__device__ int   g_off[256];
__device__ int   g_cnt[256];
__device__ int   g_cls[B];

// ---------------- helpers ----------------
__device__ __forceinline__ uint32_t smem_u32(const void* p) {
    uint32_t a;
    asm("{ .reg .u64 t; cvta.to.shared.u64 t, %1; cvt.u32.u64 %0, t; }" : "=r"(a) : "l"(p));
    return a;
}
__device__ __forceinline__ float ex2(float x) {
    float y;
    asm("ex2.approx.ftz.f32 %0, %1;" : "=f"(y) : "f"(x));
    return y;
}
__device__ __forceinline__ void cpa16(uint32_t dst, const void* src) {
    asm volatile("cp.async.cg.shared.global [%0], [%1], 16;" :: "r"(dst), "l"(src));
}
__device__ __forceinline__ void cp_commit() { asm volatile("cp.async.commit_group;" ::: "memory"); }
template<int N> __device__ __forceinline__ void cp_wait() {
    asm volatile("cp.async.wait_group %0;" :: "n"(N) : "memory");
}
__device__ __forceinline__ void ldsm4(uint32_t& r0, uint32_t& r1, uint32_t& r2, uint32_t& r3, uint32_t a) {
    asm volatile("ldmatrix.sync.aligned.m8n8.x4.shared.b16 {%0,%1,%2,%3}, [%4];"
                 : "=r"(r0), "=r"(r1), "=r"(r2), "=r"(r3) : "r"(a));
}
__device__ __forceinline__ void mma_s8(int* d, const uint32_t* a, const uint32_t* b) {
    asm volatile("mma.sync.aligned.m16n8k32.row.col.s32.s8.s8.s32 "
                 "{%0,%1,%2,%3}, {%4,%5,%6,%7}, {%8,%9}, {%0,%1,%2,%3};"
                 : "+r"(d[0]), "+r"(d[1]), "+r"(d[2]), "+r"(d[3])
                 : "r"(a[0]), "r"(a[1]), "r"(a[2]), "r"(a[3]), "r"(b[0]), "r"(b[1]));
}

// ------------- dtype detect: odd 32-bit words all zero <=> int64 ----------
__global__ void detect_kernel(const unsigned* __restrict__ words) {
    __shared__ unsigned sOr[256];
    unsigned v = 0;
    for (int k = threadIdx.x; k < B / 2; k += 256) v |= words[2 * k + 1];
    sOr[threadIdx.x] = v;
    __syncthreads();
    for (int off = 128; off; off >>= 1) {
        if (threadIdx.x < off) sOr[threadIdx.x] |= sOr[threadIdx.x + off];
        __syncthreads();
    }
    if (threadIdx.x == 0) g_lab64 = (sOr[0] == 0u) ? 1 : 0;
}

// ------------- prep: norms, labels, int8 quantize --------------------------
__global__ void prep_kernel(const float* __restrict__ emb,
                            const void* __restrict__ labels) {
    int warp = (blockIdx.x * blockDim.x + threadIdx.x) >> 5;
    int lane = threadIdx.x & 31;
    if (warp >= B) return;
    const float* row = emb + (size_t)warp * DDIM;
    float x[8];
    {
        float4 a = *reinterpret_cast<const float4*>(row + lane * 8);
        float4 b = *reinterpret_cast<const float4*>(row + lane * 8 + 4);
        x[0]=a.x; x[1]=a.y; x[2]=a.z; x[3]=a.w; x[4]=b.x; x[5]=b.y; x[6]=b.z; x[7]=b.w;
    }
    float s = 0.f, amax = 0.f;
#pragma unroll
    for (int e = 0; e < 8; ++e) {
        s = fmaf(x[e], x[e], s);
        amax = fmaxf(amax, fabsf(x[e]));
    }
#pragma unroll
    for (int off = 16; off; off >>= 1) {
        s += __shfl_xor_sync(0xffffffffu, s, off);
        amax = fmaxf(amax, __shfl_xor_sync(0xffffffffu, amax, off));
    }
    float scale = amax * (1.0f / 127.0f);
    float inv = 127.0f / amax;
    unsigned u0 = 0, u1 = 0;
#pragma unroll
    for (int e = 0; e < 4; ++e) {
        int q = __float2int_rn(x[e] * inv);
        u0 |= ((unsigned)q & 0xffu) << (e * 8);
    }
#pragma unroll
    for (int e = 0; e < 4; ++e) {
        int q = __float2int_rn(x[4 + e] * inv);
        u1 |= ((unsigned)q & 0xffu) << (e * 8);
    }
    g_q[warp * 32 + lane] = make_uint2(u0, u1);
    if (lane == 0) {
        g_basec[warp]  = -10.0f * s;
        g_basel2[warp] = -10.0f * 1.4426950408889634f * s;
        g_scale[warp]  = scale;
        int lab = g_lab64 ? (int)((const long long*)labels)[warp]
                          : ((const int*)labels)[warp];
        g_lab[warp] = lab;
    }
}

// ------------- class bucketing -------------
__global__ void sortclass_kernel() {
    __shared__ int h[256], off[256];
    int t = threadIdx.x;
    h[t] = 0;
    __syncthreads();
    for (int i = t; i < B; i += 256) atomicAdd(&h[g_lab[i] & 255], 1);
    __syncthreads();
    if (t == 0) {
        int acc = 0;
        for (int c = 0; c < 256; ++c) { off[c] = acc; acc += h[c]; }
    }
    __syncthreads();
    g_cnt[t] = h[t];
    g_off[t] = off[t];
    h[t] = off[t];
    __syncthreads();
    for (int i = t; i < B; i += 256) {
        int pos = atomicAdd(&h[g_lab[i] & 255], 1);
        g_cls[pos] = i;
    }
}

// ------- threefry2x32, JAX partitionable mode, key=(0,42) ------------------
__device__ __forceinline__ unsigned rotl32(unsigned x, int r) {
    return __funnelshift_l(x, x, r);
}
__device__ __forceinline__ unsigned threefry_bits(unsigned idx) {
    const unsigned ks0 = 0u, ks1 = 42u, ks2 = 0u ^ 42u ^ 0x1BD11BDAu;
    unsigned x0 = 0u + ks0, x1 = idx + ks1;
#define TFR(r) { x0 += x1; x1 = rotl32(x1, r); x1 ^= x0; }
    TFR(13) TFR(15) TFR(26) TFR(6)   x0 += ks1; x1 += ks2 + 1u;
    TFR(17) TFR(29) TFR(16) TFR(24)  x0 += ks2; x1 += ks0 + 2u;
    TFR(13) TFR(15) TFR(26) TFR(6)   x0 += ks0; x1 += ks1 + 3u;
    TFR(17) TFR(29) TFR(16) TFR(24)  x0 += ks1; x1 += ks2 + 4u;
    TFR(13) TFR(15) TFR(26) TFR(6)   x0 += ks2; x1 += ks0 + 5u;
#undef TFR
    return x0 ^ x1;
}

// ------------- positive selection: warp per row over its class list --------
__global__ void select_kernel() {
    int warp = (blockIdx.x * blockDim.x + threadIdx.x) >> 5;
    int lane = threadIdx.x & 31;
    if (warp >= B) return;
    int i = warp;
    int lab = g_lab[i] & 255;
    int base = g_off[lab], n = g_cnt[lab];
    unsigned bv = 0; int bj = -1;
    for (int t = lane; t < n; t += 32) {
        int j = g_cls[base + t];
        if (j == i) continue;
        unsigned v = threefry_bits((unsigned)(i * B + j)) >> 9;
        if (bj < 0 || v > bv || (v == bv && j < bj)) { bv = v; bj = j; }
    }
    const unsigned full = 0xffffffffu;
#pragma unroll
    for (int off = 16; off; off >>= 1) {
        unsigned ov = __shfl_down_sync(full, bv, off);
        int oj = __shfl_down_sync(full, bj, off);
        if (oj >= 0 && (bj < 0 || ov > bv || (ov == bv && oj < bj))) { bv = ov; bj = oj; }
    }
    if (lane == 0) {
        g_jsel[i] = bj;
        g_valid[i] = (n - 1 > 0) && (B - n > 0);
    }
}

// ------------- exact fp32 numerator: one dot per row -----------------------
__global__ void num_kernel(const float* __restrict__ emb) {
    int warp = (blockIdx.x * blockDim.x + threadIdx.x) >> 5;
    int lane = threadIdx.x & 31;
    if (warp >= B) return;
    int j = g_jsel[warp];
    if (j < 0) { if (lane == 0) g_num[warp] = 0.f; return; }
    const float* xi = emb + (size_t)warp * DDIM;
    const float* xj = emb + (size_t)j * DDIM;
    float g = 0.f;
#pragma unroll
    for (int k = 0; k < 8; k += 4) {
        float4 a = *reinterpret_cast<const float4*>(xi + lane * 8 + k);
        float4 b = *reinterpret_cast<const float4*>(xj + lane * 8 + k);
        g = fmaf(a.x, b.x, g); g = fmaf(a.y, b.y, g);
        g = fmaf(a.z, b.z, g); g = fmaf(a.w, b.w, g);
    }
#pragma unroll
    for (int off = 16; off; off >>= 1) g += __shfl_xor_sync(0xffffffffu, g, off);
    if (lane == 0)
        g_num[warp] = fminf(fmaf(20.f, g, g_basec[warp] + g_basec[j]), 0.f);
}

// ------------- main: int8 IMMA Gram (A in regs) + branchless lse -----------
__device__ __forceinline__ void stage_tile(int c0, int p, int tid, uint32_t smb) {
    uint32_t bbuf = smb + SM_B0 + (uint32_t)p * 16384u;
#pragma unroll
    for (int it = 0; it < 8; ++it) {
        int f = tid + it * THREADS;
        int n = f >> 4, v = f & 15;
        uint32_t off = (uint32_t)(n * 256 + v * 16);
        off ^= (uint32_t)(n & 7) << 4;
        cpa16(bbuf + off, (const char*)g_q + (size_t)(c0 + n) * 256 + v * 16);
    }
    uint32_t mbuf = smb + SM_META + (uint32_t)p * 768u;
    if (tid < 16)      cpa16(mbuf + tid * 16, (const char*)g_basel2 + (size_t)c0 * 4 + tid * 16);
    else if (tid < 32) cpa16(mbuf + 256 + (tid - 16) * 16, (const char*)g_lab + (size_t)c0 * 4 + (tid - 16) * 16);
    else if (tid < 48) cpa16(mbuf + 512 + (tid - 32) * 16, (const char*)g_scale + (size_t)c0 * 4 + (tid - 32) * 16);
    cp_commit();
}

__global__ void __launch_bounds__(THREADS, 2)
main_kernel() {
    extern __shared__ char smem[];
    const uint32_t smb = smem_u32(smem);
    const int tid = threadIdx.x;
    const int lane = tid & 31, wid = tid >> 5;
    const int wm = wid >> 1, wn = wid & 1;      // 2x2 warp grid, warp tile 32x32
    const int rowBase = blockIdx.y * BM;
    const int colBase = blockIdx.x * COLS_PER_CTA;
    const int split = blockIdx.x;

    // prologue: kick off tile 0, stage A (int8 rows) to smem
    stage_tile(colBase, 0, tid, smb);
#pragma unroll
    for (int it = 0; it < 8; ++it) {
        int f = tid + it * THREADS;
        int m = f >> 4, v = f & 15;
        uint4 val = *reinterpret_cast<const uint4*>(
            (const char*)g_q + (size_t)(rowBase + m) * 256 + v * 16);
        uint32_t off = (uint32_t)(m * 256 + v * 16);
        off ^= (uint32_t)(m & 7) << 4;
        *(uint4*)(smem + SM_A + off) = val;
    }
    __syncthreads();

    // hoist ALL A fragments into registers (reused for all 64 col tiles)
    uint32_t areg[KSTEPS][2][4];
#pragma unroll
    for (int ks = 0; ks < KSTEPS; ++ks)
#pragma unroll
        for (int mf = 0; mf < 2; ++mf) {
            int row = wm * 32 + mf * 16 + (lane & 15);
            uint32_t off = (uint32_t)(row * 256 + ks * 32 + ((lane >> 4) << 4));
            off ^= (uint32_t)(row & 7) << 4;
            ldsm4(areg[ks][mf][0], areg[ks][mf][1], areg[ks][mf][2], areg[ks][mf][3],
                  smb + SM_A + off);
        }

    // per-thread row metadata; (lm, ls) in shifted log2 domain
    float bi2[4], ksc[4]; int labi[4];
    float lm[4], ls[4];
#pragma unroll
    for (int r = 0; r < 4; ++r) {
        int rloc = wm * 32 + (lane >> 2) + (r & 1) * 8 + (r >> 1) * 16;
        int rg = rowBase + rloc;
        bi2[r]  = g_basel2[rg];
        ksc[r]  = K2E * g_scale[rg];
        labi[r] = g_lab[rg];
        lm[r] = MASKV; ls[r] = 0.f;
    }

    const int cq = 2 * (lane & 3);
    // B ldmatrix lane addressing (col-major rows = columns)
    const int bcol_off = ((lane >> 4) << 3) + (lane & 7);
    const int bkb_off  = ((lane >> 3) & 1) << 4;

    for (int ct = 0; ct < NT; ++ct) {
        int p = ct & 1;
        if (ct + 1 < NT) { stage_tile(colBase + (ct + 1) * BN, p ^ 1, tid, smb); cp_wait<1>(); }
        else             { cp_wait<0>(); }
        __syncthreads();

        uint32_t bbuf = smb + SM_B0 + (uint32_t)p * 16384u;
        int acc[2][4][4];
#pragma unroll
        for (int mf = 0; mf < 2; ++mf)
#pragma unroll
            for (int nf = 0; nf < 4; ++nf)
#pragma unroll
                for (int e = 0; e < 4; ++e) acc[mf][nf][e] = 0;

#pragma unroll
        for (int ks = 0; ks < KSTEPS; ++ks) {
            uint32_t b[4][2];
#pragma unroll
            for (int q = 0; q < 2; ++q) {
                int col = wn * 32 + q * 16 + bcol_off;
                uint32_t off = (uint32_t)(col * 256 + ks * 32 + bkb_off);
                off ^= (uint32_t)(col & 7) << 4;
                uint32_t t0, t1, t2, t3;
                ldsm4(t0, t1, t2, t3, bbuf + off);
                b[q * 2][0] = t0;     b[q * 2][1] = t1;
                b[q * 2 + 1][0] = t2; b[q * 2 + 1][1] = t3;
            }
#pragma unroll
            for (int mf = 0; mf < 2; ++mf)
#pragma unroll
                for (int nf = 0; nf < 4; ++nf)
                    mma_s8(acc[mf][nf], areg[ks][mf], b[nf]);
        }

        // branchless epilogue in shifted log2 domain
        const float* mBase  = (const float*)(smem + SM_META + p * 768);
        const int*   mLab   = (const int*)(smem + SM_META + p * 768 + 256);
        const float* mScale = (const float*)(smem + SM_META + p * 768 + 512);
        float cb[8], cs2[8]; int clb[8];
#pragma unroll
        for (int j = 0; j < 8; ++j) {
            int cl = wn * 32 + (j >> 1) * 8 + cq + (j & 1);
            cb[j]  = mBase[cl];
            clb[j] = mLab[cl];
            cs2[j] = mScale[cl];
        }
#pragma unroll
        for (int r = 0; r < 4; ++r) {
            int mf = r >> 1, hh = r & 1;
            float sv[8];
#pragma unroll
            for (int j = 0; j < 8; ++j) {
                float gf = __int2float_rn(acc[mf][j >> 1][hh * 2 + (j & 1)]);
                float s2 = fmaf(gf, ksc[r] * cs2[j], cb[j]);
                sv[j] = (clb[j] != labi[r]) ? s2 : MASKV;
            }
            float t0 = fmaxf(sv[0], sv[1]), t1 = fmaxf(sv[2], sv[3]);
            float t2 = fmaxf(sv[4], sv[5]), t3 = fmaxf(sv[6], sv[7]);
            float tmax = fmaxf(fmaxf(t0, t1), fmaxf(t2, t3));
            float mnew = fmaxf(lm[r], tmax);
            float a0 = ex2(sv[0] - mnew) + ex2(sv[1] - mnew);
            float a1 = ex2(sv[2] - mnew) + ex2(sv[3] - mnew);
            float a2 = ex2(sv[4] - mnew) + ex2(sv[5] - mnew);
            float a3 = ex2(sv[6] - mnew) + ex2(sv[7] - mnew);
            float asum = (a0 + a1) + (a2 + a3);
            ls[r] = fmaf(ls[r], ex2(lm[r] - mnew), asum);
            lm[r] = mnew;
        }
        __syncthreads();   // everyone done with buf p before it is re-staged
    }

    // reduce across the quad (lanes sharing the same rows) — log2 domain
#pragma unroll
    for (int r = 0; r < 4; ++r) {
#pragma unroll
        for (int off = 1; off <= 2; off <<= 1) {
            float mo = __shfl_xor_sync(0xffffffffu, lm[r], off);
            float so = __shfl_xor_sync(0xffffffffu, ls[r], off);
            float mn = fmaxf(lm[r], mo);
            ls[r] = ls[r] * ex2(lm[r] - mn) + so * ex2(mo - mn);
            lm[r] = mn;
        }
    }
    // reduce across the 2 n-warps (un-shift by +bi2 at write)
    float2* red = (float2*)(smem + SM_RED);
    if ((lane & 3) == 0) {
#pragma unroll
        for (int r = 0; r < 4; ++r) {
            int rloc = wm * 32 + (lane >> 2) + (r & 1) * 8 + (r >> 1) * 16;
            red[wn * 64 + rloc] = make_float2(lm[r] + bi2[r], ls[r]);
        }
    }
    __syncthreads();
    if (tid < 64) {
        float2 v0 = red[tid], v1 = red[64 + tid];
        float m = fmaxf(v0.x, v1.x);
        float s = v0.y * ex2(v0.x - m) + v1.y * ex2(v1.x - m);
        g_pm[split][rowBase + tid] = m;
        g_ps[split][rowBase + tid] = s;
    }
}

// ---------------- finalize: combine splits (log2), masked mean -------------
__global__ void finalize_kernel(float* __restrict__ out) {
    __shared__ double ssum[256];
    __shared__ int    scnt[256];
    int tid = threadIdx.x;
    double acc = 0.0; int cnt = 0;
    for (int r = tid; r < B; r += 256) {
        if (g_valid[r]) {
            float m0 = g_pm[0][r], m1 = g_pm[1][r];
            float m = fmaxf(m0, m1);
            float s = g_ps[0][r] * ex2(m0 - m) + g_ps[1][r] * ex2(m1 - m);
            float denom = (m + __log2f(s)) * LN2;   // back to ln domain
            acc += (double)(denom - g_num[r]);
            cnt++;
        }
    }
    ssum[tid] = acc; scnt[tid] = cnt;
    __syncthreads();
    for (int off = 128; off; off >>= 1) {
        if (tid < off) { ssum[tid] += ssum[tid + off]; scnt[tid] += scnt[tid + off]; }
        __syncthreads();
    }
    if (tid == 0)
        out[0] = (scnt[0] > 0) ? (float)(ssum[0] / (double)scnt[0]) : 0.0f;
}

// ---------------------------------------------------------------------------
extern "C" void kernel_launch(void* const* d_in, const int* in_sizes, int n_in,
                              void* d_out, int out_size) {
    const float* emb    = (const float*)d_in[0];
    const void*  labels = d_in[1];

    cudaFuncSetAttribute(main_kernel,
                         cudaFuncAttributeMaxDynamicSharedMemorySize, SM_TOTAL);

    detect_kernel<<<1, 256>>>((const unsigned*)labels);
    prep_kernel<<<B / 8, 256>>>(emb, labels);
    sortclass_kernel<<<1, 256>>>();
    select_kernel<<<B / 8, 256>>>();
    num_kernel<<<B / 8, 256>>>(emb);
    main_kernel<<<dim3(COLSPLIT, B / BM), THREADS, SM_TOTAL>>>();
    finalize_kernel<<<1, 256>>>((float*)d_out);
}

// round 17
// speedup vs baseline: 1.8941x; 1.8941x over previous
#include <cuda_runtime.h>
#include <cuda_bf16.h>
#include <cstdint>

#define B     8192
#define DDIM  256
#define BM    64
#define BN    64
#define NBLK  128                     // 8192/64 row blocks
#define KSTEPS 16                     // K = 256, pure bf16 hi
#define THREADS 128
#define K2E   28.853900817779268f     // 20 * log2(e)
#define LN2   0.6931471805599453f
#define MASKV (-1e38f)
// SMEM layout (bytes)
#define SM_A    0                     // 64 rows * 512 B = 32768
#define SM_B0   32768                 // 64 * 512 B = 32768
#define SM_B1   65536
#define SM_META 98304                 // 2 * (64 f32 base2 + 64 i32 lab) = 1024
#define SM_RED  99328                 // 128 * float2 = 1024 (loop: sTP; end: red)
#define SM_TOTAL 100352

// ---------------- scratch ----------------
__device__ uint4  g_ehi4[B * DDIM / 8];
__device__ float  g_basec[B];      // -10*||x||^2           (ln domain)
__device__ float  g_basel2[B];     // -10*log2(e)*||x||^2   (log2 domain)
__device__ int    g_lab[B];
__device__ int    g_jsel[B];
__device__ int    g_valid[B];
__device__ float  g_num[B];
__device__ float  g_den[B];
__device__ float  g_pm[2][B];      // own-row partials (2 halves), absolute log2
__device__ float  g_ps[2][B];
__device__ float2 g_tp[63 * B];    // transposed partials, slot d-1, absolute log2
__device__ int    g_lab64;
__device__ int    g_off[256];
__device__ int    g_cnt[256];
__device__ int    g_cls[B];

// ---------------- helpers ----------------
__device__ __forceinline__ uint32_t smem_u32(const void* p) {
    uint32_t a;
    asm("{ .reg .u64 t; cvta.to.shared.u64 t, %1; cvt.u32.u64 %0, t; }" : "=r"(a) : "l"(p));
    return a;
}
__device__ __forceinline__ float ex2(float x) {
    float y;
    asm("ex2.approx.ftz.f32 %0, %1;" : "=f"(y) : "f"(x));
    return y;
}
__device__ __forceinline__ void cpa16(uint32_t dst, const void* src) {
    asm volatile("cp.async.cg.shared.global [%0], [%1], 16;" :: "r"(dst), "l"(src));
}
__device__ __forceinline__ void cp_commit() { asm volatile("cp.async.commit_group;" ::: "memory"); }
template<int N> __device__ __forceinline__ void cp_wait() {
    asm volatile("cp.async.wait_group %0;" :: "n"(N) : "memory");
}
__device__ __forceinline__ void ldsm4(uint32_t& r0, uint32_t& r1, uint32_t& r2, uint32_t& r3, uint32_t a) {
    asm volatile("ldmatrix.sync.aligned.m8n8.x4.shared.b16 {%0,%1,%2,%3}, [%4];"
                 : "=r"(r0), "=r"(r1), "=r"(r2), "=r"(r3) : "r"(a));
}
__device__ __forceinline__ void mma16816(float* d, const uint32_t* a, const uint32_t* b) {
    asm volatile("mma.sync.aligned.m16n8k16.row.col.f32.bf16.bf16.f32 "
                 "{%0,%1,%2,%3}, {%4,%5,%6,%7}, {%8,%9}, {%0,%1,%2,%3};"
                 : "+f"(d[0]), "+f"(d[1]), "+f"(d[2]), "+f"(d[3])
                 : "r"(a[0]), "r"(a[1]), "r"(a[2]), "r"(a[3]), "r"(b[0]), "r"(b[1]));
}

// ------------- dtype detect: odd 32-bit words all zero <=> int64 ----------
__global__ void detect_kernel(const unsigned* __restrict__ words) {
    __shared__ unsigned sOr[256];
    unsigned v = 0;
    for (int k = threadIdx.x; k < B / 2; k += 256) v |= words[2 * k + 1];
    sOr[threadIdx.x] = v;
    __syncthreads();
    for (int off = 128; off; off >>= 1) {
        if (threadIdx.x < off) sOr[threadIdx.x] |= sOr[threadIdx.x + off];
        __syncthreads();
    }
    if (threadIdx.x == 0) g_lab64 = (sOr[0] == 0u) ? 1 : 0;
}

// ------------- prep: norms, labels, bf16 convert ---------------------------
__global__ void prep_kernel(const float* __restrict__ emb,
                            const void* __restrict__ labels) {
    int warp = (blockIdx.x * blockDim.x + threadIdx.x) >> 5;
    int lane = threadIdx.x & 31;
    if (warp >= B) return;
    const float* row = emb + (size_t)warp * DDIM;
    float x[8];
    {
        float4 a = *reinterpret_cast<const float4*>(row + lane * 8);
        float4 b = *reinterpret_cast<const float4*>(row + lane * 8 + 4);
        x[0]=a.x; x[1]=a.y; x[2]=a.z; x[3]=a.w; x[4]=b.x; x[5]=b.y; x[6]=b.z; x[7]=b.w;
    }
    float s = 0.f;
    unsigned hu[4];
#pragma unroll
    for (int e = 0; e < 8; e += 2) {
        __nv_bfloat16 h0 = __float2bfloat16(x[e]);
        __nv_bfloat16 h1 = __float2bfloat16(x[e + 1]);
        hu[e >> 1] = (unsigned)__bfloat16_as_ushort(h0) | ((unsigned)__bfloat16_as_ushort(h1) << 16);
        s = fmaf(x[e], x[e], s);
        s = fmaf(x[e + 1], x[e + 1], s);
    }
    g_ehi4[warp * 32 + lane] = make_uint4(hu[0], hu[1], hu[2], hu[3]);
#pragma unroll
    for (int off = 16; off; off >>= 1) s += __shfl_xor_sync(0xffffffffu, s, off);
    if (lane == 0) {
        g_basec[warp]  = -10.0f * s;
        g_basel2[warp] = -10.0f * 1.4426950408889634f * s;
        int lab = g_lab64 ? (int)((const long long*)labels)[warp]
                          : ((const int*)labels)[warp];
        g_lab[warp] = lab;
    }
}

// ------------- class bucketing -------------
__global__ void sortclass_kernel() {
    __shared__ int h[256], off[256];
    int t = threadIdx.x;
    h[t] = 0;
    __syncthreads();
    for (int i = t; i < B; i += 256) atomicAdd(&h[g_lab[i] & 255], 1);
    __syncthreads();
    if (t == 0) {
        int acc = 0;
        for (int c = 0; c < 256; ++c) { off[c] = acc; acc += h[c]; }
    }
    __syncthreads();
    g_cnt[t] = h[t];
    g_off[t] = off[t];
    h[t] = off[t];
    __syncthreads();
    for (int i = t; i < B; i += 256) {
        int pos = atomicAdd(&h[g_lab[i] & 255], 1);
        g_cls[pos] = i;
    }
}

// ------- threefry2x32, JAX partitionable mode, key=(0,42) ------------------
__device__ __forceinline__ unsigned rotl32(unsigned x, int r) {
    return __funnelshift_l(x, x, r);
}
__device__ __forceinline__ unsigned threefry_bits(unsigned idx) {
    const unsigned ks0 = 0u, ks1 = 42u, ks2 = 0u ^ 42u ^ 0x1BD11BDAu;
    unsigned x0 = 0u + ks0, x1 = idx + ks1;
#define TFR(r) { x0 += x1; x1 = rotl32(x1, r); x1 ^= x0; }
    TFR(13) TFR(15) TFR(26) TFR(6)   x0 += ks1; x1 += ks2 + 1u;
    TFR(17) TFR(29) TFR(16) TFR(24)  x0 += ks2; x1 += ks0 + 2u;
    TFR(13) TFR(15) TFR(26) TFR(6)   x0 += ks0; x1 += ks1 + 3u;
    TFR(17) TFR(29) TFR(16) TFR(24)  x0 += ks1; x1 += ks2 + 4u;
    TFR(13) TFR(15) TFR(26) TFR(6)   x0 += ks2; x1 += ks0 + 5u;
#undef TFR
    return x0 ^ x1;
}

// ------------- positive selection: warp per row over its class list --------
__global__ void select_kernel() {
    int warp = (blockIdx.x * blockDim.x + threadIdx.x) >> 5;
    int lane = threadIdx.x & 31;
    if (warp >= B) return;
    int i = warp;
    int lab = g_lab[i] & 255;
    int base = g_off[lab], n = g_cnt[lab];
    unsigned bv = 0; int bj = -1;
    for (int t = lane; t < n; t += 32) {
        int j = g_cls[base + t];
        if (j == i) continue;
        unsigned v = threefry_bits((unsigned)(i * B + j)) >> 9;
        if (bj < 0 || v > bv || (v == bv && j < bj)) { bv = v; bj = j; }
    }
    const unsigned full = 0xffffffffu;
#pragma unroll
    for (int off = 16; off; off >>= 1) {
        unsigned ov = __shfl_down_sync(full, bv, off);
        int oj = __shfl_down_sync(full, bj, off);
        if (oj >= 0 && (bj < 0 || ov > bv || (ov == bv && oj < bj))) { bv = ov; bj = oj; }
    }
    if (lane == 0) {
        g_jsel[i] = bj;
        g_valid[i] = (n - 1 > 0) && (B - n > 0);
    }
}

// ------------- exact fp32 numerator: one dot per row -----------------------
__global__ void num_kernel(const float* __restrict__ emb) {
    int warp = (blockIdx.x * blockDim.x + threadIdx.x) >> 5;
    int lane = threadIdx.x & 31;
    if (warp >= B) return;
    int j = g_jsel[warp];
    if (j < 0) { if (lane == 0) g_num[warp] = 0.f; return; }
    const float* xi = emb + (size_t)warp * DDIM;
    const float* xj = emb + (size_t)j * DDIM;
    float g = 0.f;
#pragma unroll
    for (int k = 0; k < 8; k += 4) {
        float4 a = *reinterpret_cast<const float4*>(xi + lane * 8 + k);
        float4 b = *reinterpret_cast<const float4*>(xj + lane * 8 + k);
        g = fmaf(a.x, b.x, g); g = fmaf(a.y, b.y, g);
        g = fmaf(a.z, b.z, g); g = fmaf(a.w, b.w, g);
    }
#pragma unroll
    for (int off = 16; off; off >>= 1) g += __shfl_xor_sync(0xffffffffu, g, off);
    if (lane == 0)
        g_num[warp] = fminf(fmaf(20.f, g, g_basec[warp] + g_basec[j]), 0.f);
}

// ------------- main: symmetric bf16 HMMA Gram + dual-view fused lse --------
__device__ __forceinline__ void stage_tile(int c0, int p, int tid, uint32_t smb) {
    uint32_t bbuf = smb + SM_B0 + (uint32_t)p * 32768u;
#pragma unroll
    for (int it = 0; it < 16; ++it) {
        int f = tid + it * THREADS;
        int n = f >> 5, v = f & 31;
        uint32_t off = (uint32_t)(n * 512 + v * 16);
        off ^= (uint32_t)(n & 7) << 4;
        cpa16(bbuf + off, g_ehi4 + (size_t)(c0 + n) * 32 + v);
    }
    uint32_t mbuf = smb + SM_META + (uint32_t)p * 512u;
    if (tid < 16)      cpa16(mbuf + tid * 16, (const char*)g_basel2 + (size_t)c0 * 4 + tid * 16);
    else if (tid < 32) cpa16(mbuf + 256 + (tid - 16) * 16, (const char*)g_lab + (size_t)c0 * 4 + (tid - 16) * 16);
    cp_commit();
}

__global__ void __launch_bounds__(THREADS, 2)
main_kernel() {
    extern __shared__ char smem[];
    const uint32_t smb = smem_u32(smem);
    const int tid = threadIdx.x;
    const int lane = tid & 31, wid = tid >> 5;
    const int wm = wid >> 1, wn = wid & 1;      // 2x2 warp grid, warp tile 32x32
    const int half = blockIdx.x;                // 0: d=0..32, 1: d=33..64
    const int kblk = blockIdx.y;                // row block
    const int rowBase = kblk * BM;
    const int dstart = half ? 33 : 0;
    const int ntiles = half ? 32 : 33;

    // prologue: kick off tile 0, stage A to smem
    stage_tile((((kblk + dstart) & (NBLK - 1)) * BN), 0, tid, smb);
#pragma unroll
    for (int it = 0; it < 16; ++it) {
        int f = tid + it * THREADS;
        int m = f >> 5, v = f & 31;
        uint4 val = g_ehi4[(size_t)(rowBase + m) * 32 + v];
        uint32_t off = (uint32_t)(m * 512 + v * 16);
        off ^= (uint32_t)(m & 7) << 4;
        *(uint4*)(smem + SM_A + off) = val;
    }
    __syncthreads();

    // hoist ALL A fragments into registers
    const int arow = wm * 32 + (lane & 15);
    const uint32_t aswz = (uint32_t)(lane & 7) << 4;
    const uint32_t aoff0 = (uint32_t)(arow * 512 + ((lane >> 4) * 16));
    uint32_t areg[KSTEPS][2][4];
#pragma unroll
    for (int ks = 0; ks < KSTEPS; ++ks)
#pragma unroll
        for (int mf = 0; mf < 2; ++mf) {
            uint32_t off = (aoff0 + (uint32_t)(mf * 8192 + ks * 32)) ^ aswz;
            ldsm4(areg[ks][mf][0], areg[ks][mf][1], areg[ks][mf][2], areg[ks][mf][3],
                  smb + SM_A + off);
        }

    // per-thread row metadata; (lm, ls) in shifted log2 domain
    float bi2[4]; int labi[4];
    float lm[4], ls[4];
#pragma unroll
    for (int r = 0; r < 4; ++r) {
        int rloc = wm * 32 + (lane >> 2) + (r & 1) * 8 + (r >> 1) * 16;
        int rg = rowBase + rloc;
        bi2[r]  = g_basel2[rg];
        labi[r] = g_lab[rg];
        lm[r] = MASKV; ls[r] = 0.f;
    }

    const int brow = ((lane >> 4) << 3) + (lane & 7);
    const uint32_t boff0 = (uint32_t)((wn * 32 + brow) * 512 + (((lane >> 3) & 1) * 16));
    const int cq = 2 * (lane & 3);
    float2* sTP = (float2*)(smem + SM_RED);      // 128 float2, reused per tile

    for (int ct = 0; ct < ntiles; ++ct) {
        int p = ct & 1;
        int d = dstart + ct;
        int jblk = (kblk + d) & (NBLK - 1);
        if (ct + 1 < ntiles) {
            stage_tile((((kblk + d + 1) & (NBLK - 1)) * BN), p ^ 1, tid, smb);
            cp_wait<1>();
        } else {
            cp_wait<0>();
        }
        __syncthreads();

        uint32_t bbuf = smb + SM_B0 + (uint32_t)p * 32768u;
        float acc[2][4][4];
#pragma unroll
        for (int mf = 0; mf < 2; ++mf)
#pragma unroll
            for (int nf = 0; nf < 4; ++nf)
#pragma unroll
                for (int e = 0; e < 4; ++e) acc[mf][nf][e] = 0.f;

#pragma unroll
        for (int ks = 0; ks < KSTEPS; ++ks) {
            uint32_t b[4][2];
#pragma unroll
            for (int nf2 = 0; nf2 < 2; ++nf2) {
                uint32_t off = (boff0 + (uint32_t)(nf2 * 8192 + ks * 32)) ^ aswz;
                uint32_t t0, t1, t2, t3;
                ldsm4(t0, t1, t2, t3, bbuf + off);
                b[nf2 * 2][0] = t0; b[nf2 * 2][1] = t1;
                b[nf2 * 2 + 1][0] = t2; b[nf2 * 2 + 1][1] = t3;
            }
#pragma unroll
            for (int mf = 0; mf < 2; ++mf)
#pragma unroll
                for (int nf = 0; nf < 4; ++nf)
                    mma16816(acc[mf][nf], areg[ks][mf], b[nf]);
        }

        const float* mBase = (const float*)(smem + SM_META + p * 512);
        const int*   mLab  = (const int*)(smem + SM_META + p * 512 + 256);
        float cb[8]; int clb[8];
#pragma unroll
        for (int j = 0; j < 8; ++j) {
            int cl = wn * 32 + (j >> 1) * 8 + cq + (j & 1);
            cb[j]  = mBase[cl];
            clb[j] = mLab[cl];
        }

        // ---- row-view fold (shifted by bi2, branchless) ----
#pragma unroll
        for (int r = 0; r < 4; ++r) {
            int mf = r >> 1, hh = r & 1;
            float sv[8];
#pragma unroll
            for (int j = 0; j < 8; ++j) {
                float s2 = fmaf(K2E, acc[mf][j >> 1][hh * 2 + (j & 1)], cb[j]);
                sv[j] = (clb[j] != labi[r]) ? s2 : MASKV;
            }
            float t0 = fmaxf(sv[0], sv[1]), t1 = fmaxf(sv[2], sv[3]);
            float t2 = fmaxf(sv[4], sv[5]), t3 = fmaxf(sv[6], sv[7]);
            float tmax = fmaxf(fmaxf(t0, t1), fmaxf(t2, t3));
            float mnew = fmaxf(lm[r], tmax);
            float a0 = ex2(sv[0] - mnew) + ex2(sv[1] - mnew);
            float a1 = ex2(sv[2] - mnew) + ex2(sv[3] - mnew);
            float a2 = ex2(sv[4] - mnew) + ex2(sv[5] - mnew);
            float a3 = ex2(sv[6] - mnew) + ex2(sv[7] - mnew);
            ls[r] = fmaf(ls[r], ex2(lm[r] - mnew), (a0 + a1) + (a2 + a3));
            lm[r] = mnew;
        }

        // ---- transposed-view fold (shifted by cb; skip d=0 and d=64) ----
        if (d != 0 && d != 64) {
            float tm[8], ts[8];
#pragma unroll
            for (int j = 0; j < 8; ++j) {
                int nf = j >> 1, e = j & 1;
                float cv0 = (clb[j] != labi[0]) ? fmaf(K2E, acc[0][nf][e], bi2[0]) : MASKV;
                float cv1 = (clb[j] != labi[1]) ? fmaf(K2E, acc[0][nf][2 + e], bi2[1]) : MASKV;
                float cv2 = (clb[j] != labi[2]) ? fmaf(K2E, acc[1][nf][e], bi2[2]) : MASKV;
                float cv3 = (clb[j] != labi[3]) ? fmaf(K2E, acc[1][nf][2 + e], bi2[3]) : MASKV;
                float mj = fmaxf(fmaxf(cv0, cv1), fmaxf(cv2, cv3));
                tm[j] = mj;
                ts[j] = (ex2(cv0 - mj) + ex2(cv1 - mj)) + (ex2(cv2 - mj) + ex2(cv3 - mj));
            }
            // butterfly over lane>>2 (8 row-groups within the wm half)
#pragma unroll
            for (int st = 4; st <= 16; st <<= 1) {
#pragma unroll
                for (int j = 0; j < 8; ++j) {
                    float om = __shfl_xor_sync(0xffffffffu, tm[j], st);
                    float os = __shfl_xor_sync(0xffffffffu, ts[j], st);
                    float mn = fmaxf(tm[j], om);
                    ts[j] = ts[j] * ex2(tm[j] - mn) + os * ex2(om - mn);
                    tm[j] = mn;
                }
            }
            if ((lane >> 2) == 0) {
#pragma unroll
                for (int j = 0; j < 8; ++j) {
                    int cl = wn * 32 + (j >> 1) * 8 + cq + (j & 1);
                    sTP[wm * 64 + cl] = make_float2(tm[j], ts[j]);
                }
            }
            __syncthreads();
            if (tid < 64) {
                float2 v0 = sTP[tid], v1 = sTP[64 + tid];
                float mn = fmaxf(v0.x, v1.x);
                float ss = v0.y * ex2(v0.x - mn) + v1.y * ex2(v1.x - mn);
                g_tp[(size_t)(d - 1) * B + jblk * 64 + tid] =
                    make_float2(mn + mBase[tid], ss);   // absolute log2
            }
        }
        __syncthreads();   // buf p + sTP free for next tile
    }

    // reduce row-view across the quad, then across the 2 n-warps
#pragma unroll
    for (int r = 0; r < 4; ++r) {
#pragma unroll
        for (int off = 1; off <= 2; off <<= 1) {
            float mo = __shfl_xor_sync(0xffffffffu, lm[r], off);
            float so = __shfl_xor_sync(0xffffffffu, ls[r], off);
            float mn = fmaxf(lm[r], mo);
            ls[r] = ls[r] * ex2(lm[r] - mn) + so * ex2(mo - mn);
            lm[r] = mn;
        }
    }
    float2* red = (float2*)(smem + SM_RED);
    if ((lane & 3) == 0) {
#pragma unroll
        for (int r = 0; r < 4; ++r) {
            int rloc = wm * 32 + (lane >> 2) + (r & 1) * 8 + (r >> 1) * 16;
            red[wn * 64 + rloc] = make_float2(lm[r] + bi2[r], ls[r]);
        }
    }
    __syncthreads();
    if (tid < 64) {
        float2 v0 = red[tid], v1 = red[64 + tid];
        float m = fmaxf(v0.x, v1.x);
        float s = v0.y * ex2(v0.x - m) + v1.y * ex2(v1.x - m);
        g_pm[half][rowBase + tid] = m;
        g_ps[half][rowBase + tid] = s;
    }
}

// ------------- reduce: combine 2 own + 63 transposed partials per row ------
__global__ void reduce_kernel() {
    int r = blockIdx.x * blockDim.x + threadIdx.x;
    if (r >= B) return;
    float m = g_pm[0][r], s = g_ps[0][r];
    {
        float mo = g_pm[1][r], so = g_ps[1][r];
        float mn = fmaxf(m, mo);
        s = s * ex2(m - mn) + so * ex2(mo - mn);
        m = mn;
    }
#pragma unroll 7
    for (int dd = 0; dd < 63; ++dd) {
        float2 v = g_tp[(size_t)dd * B + r];
        float mn = fmaxf(m, v.x);
        s = s * ex2(m - mn) + v.y * ex2(v.x - mn);
        m = mn;
    }
    g_den[r] = (m + __log2f(s)) * LN2;   // back to ln domain
}

// ---------------- finalize: masked mean ------------------------------------
__global__ void finalize_kernel(float* __restrict__ out) {
    __shared__ double ssum[256];
    __shared__ int    scnt[256];
    int tid = threadIdx.x;
    double acc = 0.0; int cnt = 0;
    for (int r = tid; r < B; r += 256) {
        if (g_valid[r]) {
            acc += (double)(g_den[r] - g_num[r]);
            cnt++;
        }
    }
    ssum[tid] = acc; scnt[tid] = cnt;
    __syncthreads();
    for (int off = 128; off; off >>= 1) {
        if (tid < off) { ssum[tid] += ssum[tid + off]; scnt[tid] += scnt[tid + off]; }
        __syncthreads();
    }
    if (tid == 0)
        out[0] = (scnt[0] > 0) ? (float)(ssum[0] / (double)scnt[0]) : 0.0f;
}

// ---------------------------------------------------------------------------
extern "C" void kernel_launch(void* const* d_in, const int* in_sizes, int n_in,
                              void* d_out, int out_size) {
    const float* emb    = (const float*)d_in[0];
    const void*  labels = d_in[1];

    cudaFuncSetAttribute(main_kernel,
                         cudaFuncAttributeMaxDynamicSharedMemorySize, SM_TOTAL);

    detect_kernel<<<1, 256>>>((const unsigned*)labels);
    prep_kernel<<<B / 8, 256>>>(emb, labels);
    sortclass_kernel<<<1, 256>>>();
    select_kernel<<<B / 8, 256>>>();
    num_kernel<<<B / 8, 256>>>(emb);
    main_kernel<<<dim3(2, NBLK), THREADS, SM_TOTAL>>>();
    reduce_kernel<<<B / 256, 256>>>();
    finalize_kernel<<<1, 256>>>((float*)d_out);
}